// round 14
// baseline (speedup 1.0000x reference)
#include <cuda_runtime.h>
#include <cuda_bf16.h>
#include <math.h>
#include <stdint.h>

#define Bq    8
#define Cc    384
#define Nn    4096
#define HEADS 8
#define HD    48
#define WSZ   (Cc*Cc)

// ---------------- scratch (device globals) ----------------
__device__ __nv_bfloat16 g_xs[(size_t)Bq*Cc*Nn];   // spike(x)  [b][c][n]
__device__ __nv_bfloat16 g_q [(size_t)Bq*Cc*Nn];   // spike-q bf16 (for attn)
__device__ int8_t        g_ki8[(size_t)Bq*Cc*Nn];  // 4*spike-k int (0..4)
__device__ int8_t        g_vi8[(size_t)Bq*Cc*Nn];
__device__ __nv_bfloat16 g_a [(size_t)Bq*Cc*Nn];
__device__ __nv_bfloat16 g_whi[4*WSZ];             // stacked rows: [1536][384]
__device__ __nv_bfloat16 g_wlo[4*WSZ];
__device__ int   g_kvi[Bq*HEADS*HD*HD];            // exact integer kv sums (16x)
__device__ char  g_kvp[64*16128];                  // pre-swizzled kv digit planes
__device__ float g_s [4*Cc];
__device__ float g_t [4*Cc];

__device__ __forceinline__ float spikef(float x) {
    return rintf(fminf(fmaxf(x, 0.0f), 4.0f)) * 0.25f;
}

// ---------------- PTX helpers (sm_80-class ISA, compiles on plain sm_103) ----
__device__ __forceinline__ uint32_t smem_u32(const void* p) {
    uint32_t a;
    asm("{ .reg .u64 t; cvta.to.shared.u64 t, %1; cvt.u32.u64 %0, t; }" : "=r"(a) : "l"(p));
    return a;
}
__device__ __forceinline__ void cp16(uint32_t s, const void* g) {
    asm volatile("cp.async.cg.shared.global [%0], [%1], 16;" :: "r"(s), "l"(g));
}
__device__ __forceinline__ void ldsm4(uint32_t* r, uint32_t a) {
    asm volatile("ldmatrix.sync.aligned.m8n8.x4.shared.b16 {%0,%1,%2,%3}, [%4];"
        : "=r"(r[0]), "=r"(r[1]), "=r"(r[2]), "=r"(r[3]) : "r"(a));
}
__device__ __forceinline__ void ldsm4t(uint32_t* r, uint32_t a) {
    asm volatile("ldmatrix.sync.aligned.m8n8.x4.trans.shared.b16 {%0,%1,%2,%3}, [%4];"
        : "=r"(r[0]), "=r"(r[1]), "=r"(r[2]), "=r"(r[3]) : "r"(a));
}
__device__ __forceinline__ void mma16816(float* d, const uint32_t* a, const uint32_t* b) {
    asm volatile(
        "mma.sync.aligned.m16n8k16.row.col.f32.bf16.bf16.f32 "
        "{%0,%1,%2,%3}, {%4,%5,%6,%7}, {%8,%9}, {%0,%1,%2,%3};"
        : "+f"(d[0]), "+f"(d[1]), "+f"(d[2]), "+f"(d[3])
        : "r"(a[0]), "r"(a[1]), "r"(a[2]), "r"(a[3]), "r"(b[0]), "r"(b[1]));
}
__device__ __forceinline__ int dp4a_s(int a, int b, int c) {
    asm("dp4a.s32.s32 %0, %1, %2, %3;" : "=r"(c) : "r"(a), "r"(b), "r"(c));
    return c;
}

// ---------------- prep_all: params + kv-zero + weight split + spike(x) ------
#define PREP_SPLIT0 8
#define PREP_SPIKE0 2312
#define PREP_BLOCKS 14600

__global__ __launch_bounds__(256)
void prep_all(
    const float* __restrict__ x, __nv_bfloat16* __restrict__ xs,
    const float* w0, const float* w1, const float* w2, const float* w3,
    __nv_bfloat16* __restrict__ hi, __nv_bfloat16* __restrict__ lo,
    const float* g0, const float* b0, const float* m0, const float* v0,
    const float* g1, const float* b1, const float* m1, const float* v1,
    const float* g2, const float* b2, const float* m2, const float* v2,
    const float* g3, const float* b3, const float* m3, const float* v3,
    float* __restrict__ s, float* __restrict__ t)
{
    const int bx = blockIdx.x, tid = threadIdx.x;
    if (bx >= PREP_SPIKE0) {
        int i = (bx - PREP_SPIKE0) * 256 + tid;
        float4 v = reinterpret_cast<const float4*>(x)[i];
        __nv_bfloat162 a = __floats2bfloat162_rn(spikef(v.x), spikef(v.y));
        __nv_bfloat162 b = __floats2bfloat162_rn(spikef(v.z), spikef(v.w));
        uint2 pk;
        pk.x = *reinterpret_cast<uint32_t*>(&a);
        pk.y = *reinterpret_cast<uint32_t*>(&b);
        reinterpret_cast<uint2*>(xs)[i] = pk;
    } else if (bx >= PREP_SPLIT0) {
        int i = (bx - PREP_SPLIT0) * 256 + tid;
        int p = i / WSZ, r = i - p * WSZ;
        const float* w = p == 0 ? w0 : p == 1 ? w1 : p == 2 ? w2 : w3;
        float v = w[r];
        __nv_bfloat16 h = __float2bfloat16(v);
        hi[i] = h;
        lo[i] = __float2bfloat16(v - __bfloat162float(h));
    } else if (bx >= 6) {
        int base = (bx - 6) * (Bq * HEADS * HD * HD / 2);
        for (int j = tid; j < Bq * HEADS * HD * HD / 2; j += 256)
            g_kvi[base + j] = 0;
    } else {
        int i = bx * 256 + tid;
        if (i < 4 * Cc) {
            int st = i / Cc, c = i - st * Cc;
            const float* ga = st == 0 ? g0 : st == 1 ? g1 : st == 2 ? g2 : g3;
            const float* be = st == 0 ? b0 : st == 1 ? b1 : st == 2 ? b2 : b3;
            const float* me = st == 0 ? m0 : st == 1 ? m1 : st == 2 ? m2 : m3;
            const float* va = st == 0 ? v0 : st == 1 ? v1 : st == 2 ? v2 : v3;
            float sv = ga[c] / sqrtf(va[c] + 1e-5f);
            s[i] = sv;
            t[i] = be[c] - me[c] * sv;
        }
    }
}

// ---------------- HMMA GEMM, 128x128, warp 64x32, k-chunk 64, 1 barrier/chunk
#define STG_B 49152            // per stage: A_hi 16K | A_lo 16K | B 16K
#define SMEM_GEMM (2*STG_B)    // 98304

__global__ __launch_bounds__(256, 2)
void gemm_hmma(const __nv_bfloat16* __restrict__ Whi, const __nv_bfloat16* __restrict__ Wlo,
               const __nv_bfloat16* __restrict__ X,
               __nv_bfloat16* __restrict__ oq, int8_t* __restrict__ ok8,
               int8_t* __restrict__ ov8, float* __restrict__ ofp,
               const float* __restrict__ sArr, const float* __restrict__ tArr,
               int mbase, int mode)
{
    extern __shared__ char smem[];
    const uint32_t sb = smem_u32(smem);
    const int tid = threadIdx.x, lane = tid & 31, wid = tid >> 5;
    const int wm = wid & 1, wn = wid >> 1;
    const int n0 = blockIdx.x * 128, m0 = mbase + blockIdx.y * 128, b = blockIdx.z;
    const __nv_bfloat16* Xb = X + (size_t)b * (Cc * Nn);

    float acc[4][4][4];
    #pragma unroll
    for (int t = 0; t < 4; ++t)
        #pragma unroll
        for (int u = 0; u < 4; ++u)
            #pragma unroll
            for (int e = 0; e < 4; ++e) acc[t][u][e] = 0.0f;

    auto load_chunk = [&](int kc, int st) {
        uint32_t base = sb + st * STG_B;
        #pragma unroll
        for (int p = 0; p < 4; ++p) {                   // A hi+lo: 128r x 8 chunks
            int idx = tid + p * 256;
            int row = idx >> 3, c = idx & 7;
            uint32_t so = row * 128 + ((c ^ (row & 7)) << 4);
            cp16(base + so, Whi + (size_t)(m0 + row) * Cc + kc * 64 + c * 8);
            cp16(base + 16384 + so, Wlo + (size_t)(m0 + row) * Cc + kc * 64 + c * 8);
        }
        #pragma unroll
        for (int p = 0; p < 4; ++p) {                   // B: 64 k-rows x 16 chunks
            int idx = tid + p * 256;
            int kr = idx >> 4, c = idx & 15;
            uint32_t so = kr * 256 + (((c & 8) | ((c & 7) ^ (kr & 7))) << 4);
            cp16(base + 32768 + so, Xb + (size_t)(kc * 64 + kr) * Nn + n0 + c * 8);
        }
        asm volatile("cp.async.commit_group;");
    };

    load_chunk(0, 0);
    const int sel = lane >> 3, l7 = lane & 7;

    for (int kc = 0; kc < 6; ++kc) {
        asm volatile("cp.async.wait_group 0;");
        __syncthreads();                       // RAW for chunk kc + WAR for kc+1's buffer
        if (kc + 1 < 6) load_chunk(kc + 1, (kc + 1) & 1);

        uint32_t base = sb + (kc & 1) * STG_B;

        #pragma unroll
        for (int h = 0; h < 4; ++h) {                   // 4 k16 halves per k64
            uint32_t bb[2][4];
            #pragma unroll
            for (int j = 0; j < 2; ++j) {
                int kr = h * 16 + (sel & 1) * 8 + l7;
                int nc = (wn * 32 + j * 16 + (sel >> 1) * 8) >> 3;
                uint32_t bd = base + 32768 + kr * 256 +
                              (((nc & 8) | ((nc & 7) ^ (kr & 7))) << 4);
                ldsm4t(bb[j], bd);
            }
            #pragma unroll
            for (int t = 0; t < 4; ++t) {
                int row = wm * 64 + t * 16 + (sel & 1) * 8 + l7;
                int kcx = h * 2 + (sel >> 1);
                uint32_t ad = base + row * 128 + ((kcx ^ (row & 7)) << 4);
                uint32_t ahi[4], alo[4];
                ldsm4(ahi, ad);
                #pragma unroll
                for (int u = 0; u < 4; ++u)
                    mma16816(acc[t][u], ahi, &bb[u >> 1][(u & 1) * 2]);
                ldsm4(alo, ad + 16384);
                #pragma unroll
                for (int u = 0; u < 4; ++u)
                    mma16816(acc[t][u], alo, &bb[u >> 1][(u & 1) * 2]);
            }
        }
    }
    // NOTE: no sync needed — mode-0 staging (34.8 KB) fits in stage-0 buffer;
    // final compute (chunk 5) reads only stage-1. But warps may still be in
    // compute(5) reading stage-1 while others stage into stage-0: disjoint.

    if (mode == 0) {
        const int st = m0 / Cc;                      // 0=q, 1=k, 2=v
        const int mloc = m0 - st * Cc;
        __nv_bfloat16* sm = reinterpret_cast<__nv_bfloat16*>(smem);
        #pragma unroll
        for (int t = 0; t < 4; ++t) {
            int r0 = wm * 64 + t * 16 + (lane >> 2);
            float s0 = sArr[m0 + r0], t0 = tArr[m0 + r0];
            float s1 = sArr[m0 + r0 + 8], t1 = tArr[m0 + r0 + 8];
            #pragma unroll
            for (int u = 0; u < 4; ++u) {
                int col = wn * 32 + u * 8 + 2 * (lane & 3);
                __nv_bfloat162 p0 = __floats2bfloat162_rn(
                    spikef(acc[t][u][0] * s0 + t0), spikef(acc[t][u][1] * s0 + t0));
                __nv_bfloat162 p1 = __floats2bfloat162_rn(
                    spikef(acc[t][u][2] * s1 + t1), spikef(acc[t][u][3] * s1 + t1));
                *reinterpret_cast<__nv_bfloat162*>(sm + r0 * 136 + col) = p0;
                *reinterpret_cast<__nv_bfloat162*>(sm + (r0 + 8) * 136 + col) = p1;
            }
        }
        __syncthreads();
        if (st == 0) {
            __nv_bfloat16* Yb = oq + (size_t)b * (Cc * Nn);
            #pragma unroll
            for (int it = 0; it < 8; ++it) {
                int idx = tid + it * 256;
                int row = idx >> 4, ci = idx & 15;
                uint4 u4 = *reinterpret_cast<const uint4*>(sm + row * 136 + ci * 8);
                *reinterpret_cast<uint4*>(
                    Yb + (size_t)(mloc + row) * Nn + n0 + ci * 8) = u4;
            }
        } else {
            int8_t* Yb = (st == 1 ? ok8 : ov8) + (size_t)b * (Cc * Nn);
            #pragma unroll
            for (int it = 0; it < 8; ++it) {
                int idx = tid + it * 256;
                int row = idx >> 4, ci = idx & 15;
                uint4 u4 = *reinterpret_cast<const uint4*>(sm + row * 136 + ci * 8);
                const __nv_bfloat16* pb = reinterpret_cast<const __nv_bfloat16*>(&u4);
                uint32_t lo = 0, hi = 0;
                #pragma unroll
                for (int z = 0; z < 4; ++z)
                    lo |= ((uint32_t)(int)(__bfloat162float(pb[z]) * 4.0f)) << (8 * z);
                #pragma unroll
                for (int z = 0; z < 4; ++z)
                    hi |= ((uint32_t)(int)(__bfloat162float(pb[4 + z]) * 4.0f)) << (8 * z);
                uint2 pk = make_uint2(lo, hi);
                *reinterpret_cast<uint2*>(
                    Yb + (size_t)(mloc + row) * Nn + n0 + ci * 8) = pk;
            }
        }
    } else {
        float* Yb = ofp + (size_t)b * (Cc * Nn);
        const int mloc = m0 - 3 * Cc;
        #pragma unroll
        for (int t = 0; t < 4; ++t) {
            int r0 = wm * 64 + t * 16 + (lane >> 2);
            float s0 = sArr[m0 + r0], t0 = tArr[m0 + r0];
            float s1 = sArr[m0 + r0 + 8], t1 = tArr[m0 + r0 + 8];
            #pragma unroll
            for (int u = 0; u < 4; ++u) {
                int col = n0 + wn * 32 + u * 8 + 2 * (lane & 3);
                float2 p0 = make_float2(acc[t][u][0] * s0 + t0, acc[t][u][1] * s0 + t0);
                float2 p1 = make_float2(acc[t][u][2] * s1 + t1, acc[t][u][3] * s1 + t1);
                *reinterpret_cast<float2*>(Yb + (size_t)(mloc + r0) * Nn + col) = p0;
                *reinterpret_cast<float2*>(Yb + (size_t)(mloc + r0 + 8) * Nn + col) = p1;
            }
        }
    }
}

// ---------------- kv via dp4a: kv[b,h,d,e] = sum_n 4k*4v (exact s32) ---------
__global__ __launch_bounds__(256)
void kv_kernel() {
    const int chunk = blockIdx.x, h = blockIdx.y, b = blockIdx.z;
    const int* kp = reinterpret_cast<const int*>(
        g_ki8 + ((size_t)b * Cc + h * HD) * Nn) + chunk * 128;
    const int* vp = reinterpret_cast<const int*>(
        g_vi8 + ((size_t)b * Cc + h * HD) * Nn) + chunk * 128;

    __shared__ int ks[64][49];
    __shared__ int vs[64][49];

    const int tid = threadIdx.x;
    const int te = tid & 15, td = tid >> 4;
    int acc[3][3] = {};

    #pragma unroll
    for (int sub = 0; sub < 2; ++sub) {
        #pragma unroll
        for (int p = 0; p < 12; ++p) {
            int i = tid + p * 256;
            int d = i >> 6, w = i & 63;
            ks[w][d] = kp[(size_t)d * (Nn / 4) + sub * 64 + w];
            vs[w][d] = vp[(size_t)d * (Nn / 4) + sub * 64 + w];
        }
        __syncthreads();
        #pragma unroll 4
        for (int w = 0; w < 64; ++w) {
            int kd[3], ve[3];
            #pragma unroll
            for (int i = 0; i < 3; ++i) kd[i] = ks[w][td * 3 + i];
            #pragma unroll
            for (int i = 0; i < 3; ++i) ve[i] = vs[w][te * 3 + i];
            #pragma unroll
            for (int i = 0; i < 3; ++i)
                #pragma unroll
                for (int j = 0; j < 3; ++j)
                    acc[i][j] = dp4a_s(kd[i], ve[j], acc[i][j]);
        }
        __syncthreads();
    }
    int* kvp = g_kvi + (size_t)(b * HEADS + h) * HD * HD;
    #pragma unroll
    for (int i = 0; i < 3; ++i)
        #pragma unroll
        for (int j = 0; j < 3; ++j)
            atomicAdd(&kvp[(td * 3 + i) * HD + te * 3 + j], acc[i][j]);
}

// ---------------- kv_split: kvi -> 3 pre-swizzled bf16 digit planes ---------
// Layout per (b,h): plane pl at pl*5376 + e*112 + d*2  (16128 B total).
__global__ __launch_bounds__(192)
void kv_split() {
    const int bh = blockIdx.x, tid = threadIdx.x;
    const int* kvp = g_kvi + (size_t)bh * HD * HD;
    char* dst = g_kvp + (size_t)bh * 16128;
    for (int i = tid; i < HD * HD; i += 192) {
        int d = i / HD, e = i - d * HD;
        float f = (float)kvp[i];                 // exact (< 2^24)
        __nv_bfloat16 hi = __float2bfloat16(f);
        float f1 = f - __bfloat162float(hi);     // exact
        __nv_bfloat16 mid = __float2bfloat16(f1);
        float f2 = f1 - __bfloat162float(mid);   // exact
        __nv_bfloat16 lo = __float2bfloat16(f2);
        char* base = dst + e * 112 + d * 2;
        *reinterpret_cast<__nv_bfloat16*>(base) = hi;
        *reinterpret_cast<__nv_bfloat16*>(base + 5376) = mid;
        *reinterpret_cast<__nv_bfloat16*>(base + 2 * 5376) = lo;
    }
}

// ---------------- attn via HMMA: a = spike(mult16 * q @ kvi) -----------------
#define A_PITCH 112
#define A_PLANE (HD * A_PITCH)
#define Q_OFF   16384
#define ATTN_SMEM (Q_OFF + HD * 256)

__global__ __launch_bounds__(192)
void attn_hmma() {
    __shared__ char smem[ATTN_SMEM];
    const uint32_t sb = smem_u32(smem);
    const int tid = threadIdx.x, lane = tid & 31, wid = tid >> 5;
    const int wm = wid >> 1, wn = wid & 1;
    const int n0 = blockIdx.x * 128, h = blockIdx.y, b = blockIdx.z;

    // q tile [48 d][128 n] + pre-split kv planes, all via cp.async
    const __nv_bfloat16* qp = g_q + ((size_t)b * Cc + h * HD) * Nn + n0;
    #pragma unroll
    for (int p = 0; p < 4; ++p) {
        int idx = tid + p * 192;
        int d = idx >> 4, c = idx & 15;
        uint32_t so = Q_OFF + d * 256 + (((c & 8) | ((c & 7) ^ (d & 7))) << 4);
        cp16(sb + so, qp + (size_t)d * Nn + c * 8);
    }
    const char* kvsrc = g_kvp + (size_t)(b * HEADS + h) * 16128;
    #pragma unroll
    for (int p = 0; p < 6; ++p) {
        int idx = tid + p * 192;
        if (idx < 1008) cp16(sb + idx * 16, kvsrc + idx * 16);
    }
    asm volatile("cp.async.commit_group;");
    asm volatile("cp.async.wait_group 0;");
    __syncthreads();

    const int sel = lane >> 3, l7 = lane & 7;

    float acc[8][4];
    #pragma unroll
    for (int u = 0; u < 8; ++u)
        #pragma unroll
        for (int e = 0; e < 4; ++e) acc[u][e] = 0.0f;

    #pragma unroll
    for (int kk = 0; kk < 3; ++kk) {
        uint32_t bb[4][4];
        #pragma unroll
        for (int j = 0; j < 4; ++j) {
            int kr = kk * 16 + (sel & 1) * 8 + l7;
            int nc = (wn * 64 + j * 16 + (sel >> 1) * 8) >> 3;
            uint32_t bd = sb + Q_OFF + kr * 256 +
                          (((nc & 8) | ((nc & 7) ^ (kr & 7))) << 4);
            ldsm4t(bb[j], bd);
        }
        int row = wm * 16 + (sel & 1) * 8 + l7;
        uint32_t ad = sb + row * A_PITCH + (kk * 2 + (sel >> 1)) * 16;
        #pragma unroll
        for (int pl = 0; pl < 3; ++pl) {
            uint32_t A[4];
            ldsm4(A, ad + pl * A_PLANE);
            #pragma unroll
            for (int u = 0; u < 8; ++u)
                mma16816(acc[u], A, &bb[u >> 1][(u & 1) * 2]);
        }
    }

    __nv_bfloat16* ap = g_a + (size_t)b * (Cc * Nn);
    const float mult16 = 0.28867513459481287f * 0.0625f;
    const int r0 = h * HD + wm * 16 + (lane >> 2);
    #pragma unroll
    for (int u = 0; u < 8; ++u) {
        int col = n0 + wn * 64 + u * 8 + 2 * (lane & 3);
        __nv_bfloat162 p0 = __floats2bfloat162_rn(
            spikef(acc[u][0] * mult16), spikef(acc[u][1] * mult16));
        __nv_bfloat162 p1 = __floats2bfloat162_rn(
            spikef(acc[u][2] * mult16), spikef(acc[u][3] * mult16));
        *reinterpret_cast<__nv_bfloat162*>(ap + (size_t)r0 * Nn + col) = p0;
        *reinterpret_cast<__nv_bfloat162*>(ap + (size_t)(r0 + 8) * Nn + col) = p1;
    }
}

// ---------------- launch ----------------
extern "C" void kernel_launch(void* const* d_in, const int* in_sizes, int n_in,
                              void* d_out, int out_size) {
    const float* x = (const float*)d_in[0];
    __nv_bfloat16 *xs, *qb, *ab, *whi, *wlo;
    int8_t *k8, *v8;
    float *sarr, *tarr;
    cudaGetSymbolAddress((void**)&xs,  g_xs);
    cudaGetSymbolAddress((void**)&qb,  g_q);
    cudaGetSymbolAddress((void**)&k8,  g_ki8);
    cudaGetSymbolAddress((void**)&v8,  g_vi8);
    cudaGetSymbolAddress((void**)&ab,  g_a);
    cudaGetSymbolAddress((void**)&whi, g_whi);
    cudaGetSymbolAddress((void**)&wlo, g_wlo);
    cudaGetSymbolAddress((void**)&sarr, g_s);
    cudaGetSymbolAddress((void**)&tarr, g_t);

    cudaFuncSetAttribute(gemm_hmma, cudaFuncAttributeMaxDynamicSharedMemorySize, SMEM_GEMM);

    prep_all<<<PREP_BLOCKS, 256>>>(
        x, xs,
        (const float*)d_in[1], (const float*)d_in[6],
        (const float*)d_in[11], (const float*)d_in[16], whi, wlo,
        (const float*)d_in[2],  (const float*)d_in[3],  (const float*)d_in[4],  (const float*)d_in[5],
        (const float*)d_in[7],  (const float*)d_in[8],  (const float*)d_in[9],  (const float*)d_in[10],
        (const float*)d_in[12], (const float*)d_in[13], (const float*)d_in[14], (const float*)d_in[15],
        (const float*)d_in[17], (const float*)d_in[18], (const float*)d_in[19], (const float*)d_in[20],
        sarr, tarr);

    // fused QKV: stacked M = 1152
    gemm_hmma<<<dim3(Nn / 128, 9, Bq), 256, SMEM_GEMM>>>(
        whi, wlo, xs, qb, k8, v8, nullptr, sarr, tarr, 0, 0);

    kv_kernel<<<dim3(8, HEADS, Bq), 256>>>();
    kv_split<<<64, 192>>>();
    attn_hmma<<<dim3(Nn / 128, HEADS, Bq), 192>>>();

    gemm_hmma<<<dim3(Nn / 128, 3, Bq), 256, SMEM_GEMM>>>(
        whi, wlo, ab, nullptr, nullptr, nullptr, (float*)d_out, sarr, tarr, 3 * Cc, 1);
}

// round 15
// speedup vs baseline: 1.0292x; 1.0292x over previous
#include <cuda_runtime.h>
#include <cuda_bf16.h>
#include <math.h>
#include <stdint.h>

#define Bq    8
#define Cc    384
#define Nn    4096
#define HEADS 8
#define HD    48
#define WSZ   (Cc*Cc)

// ---------------- scratch (device globals) ----------------
__device__ __nv_bfloat16 g_xs[(size_t)Bq*Cc*Nn];   // spike(x)  [b][c][n]
__device__ __nv_bfloat16 g_q [(size_t)Bq*Cc*Nn];   // spike-q bf16 (for attn)
__device__ int8_t        g_ki8[(size_t)Bq*Cc*Nn];  // 4*spike-k int (0..4)
__device__ int8_t        g_vi8[(size_t)Bq*Cc*Nn];
__device__ __nv_bfloat16 g_a [(size_t)Bq*Cc*Nn];
__device__ __nv_bfloat16 g_whi[4*WSZ];             // stacked rows: [1536][384]
__device__ __nv_bfloat16 g_wlo[4*WSZ];
__device__ int   g_kvi[Bq*HEADS*HD*HD];            // exact integer kv sums (16x)
__device__ char  g_kvp[64*16128];                  // pre-swizzled kv digit planes
__device__ float g_s [4*Cc];
__device__ float g_t [4*Cc];

__device__ __forceinline__ float spikef(float x) {
    return rintf(fminf(fmaxf(x, 0.0f), 4.0f)) * 0.25f;
}

// ---------------- PTX helpers (sm_80-class ISA, compiles on plain sm_103) ----
__device__ __forceinline__ uint32_t smem_u32(const void* p) {
    uint32_t a;
    asm("{ .reg .u64 t; cvta.to.shared.u64 t, %1; cvt.u32.u64 %0, t; }" : "=r"(a) : "l"(p));
    return a;
}
__device__ __forceinline__ void cp16(uint32_t s, const void* g) {
    asm volatile("cp.async.cg.shared.global [%0], [%1], 16;" :: "r"(s), "l"(g));
}
__device__ __forceinline__ void ldsm4(uint32_t* r, uint32_t a) {
    asm volatile("ldmatrix.sync.aligned.m8n8.x4.shared.b16 {%0,%1,%2,%3}, [%4];"
        : "=r"(r[0]), "=r"(r[1]), "=r"(r[2]), "=r"(r[3]) : "r"(a));
}
__device__ __forceinline__ void ldsm4t(uint32_t* r, uint32_t a) {
    asm volatile("ldmatrix.sync.aligned.m8n8.x4.trans.shared.b16 {%0,%1,%2,%3}, [%4];"
        : "=r"(r[0]), "=r"(r[1]), "=r"(r[2]), "=r"(r[3]) : "r"(a));
}
__device__ __forceinline__ void mma16816(float* d, const uint32_t* a, const uint32_t* b) {
    asm volatile(
        "mma.sync.aligned.m16n8k16.row.col.f32.bf16.bf16.f32 "
        "{%0,%1,%2,%3}, {%4,%5,%6,%7}, {%8,%9}, {%0,%1,%2,%3};"
        : "+f"(d[0]), "+f"(d[1]), "+f"(d[2]), "+f"(d[3])
        : "r"(a[0]), "r"(a[1]), "r"(a[2]), "r"(a[3]), "r"(b[0]), "r"(b[1]));
}
__device__ __forceinline__ int dp4a_s(int a, int b, int c) {
    asm("dp4a.s32.s32 %0, %1, %2, %3;" : "=r"(c) : "r"(a), "r"(b), "r"(c));
    return c;
}

// ---------------- prep_all: params + kv-zero + weight split + spike(x) ------
#define PREP_SPLIT0 8
#define PREP_SPIKE0 2312
#define PREP_BLOCKS 14600

__global__ __launch_bounds__(256)
void prep_all(
    const float* __restrict__ x, __nv_bfloat16* __restrict__ xs,
    const float* w0, const float* w1, const float* w2, const float* w3,
    __nv_bfloat16* __restrict__ hi, __nv_bfloat16* __restrict__ lo,
    const float* g0, const float* b0, const float* m0, const float* v0,
    const float* g1, const float* b1, const float* m1, const float* v1,
    const float* g2, const float* b2, const float* m2, const float* v2,
    const float* g3, const float* b3, const float* m3, const float* v3,
    float* __restrict__ s, float* __restrict__ t)
{
    const int bx = blockIdx.x, tid = threadIdx.x;
    if (bx >= PREP_SPIKE0) {
        int i = (bx - PREP_SPIKE0) * 256 + tid;
        float4 v = reinterpret_cast<const float4*>(x)[i];
        __nv_bfloat162 a = __floats2bfloat162_rn(spikef(v.x), spikef(v.y));
        __nv_bfloat162 b = __floats2bfloat162_rn(spikef(v.z), spikef(v.w));
        uint2 pk;
        pk.x = *reinterpret_cast<uint32_t*>(&a);
        pk.y = *reinterpret_cast<uint32_t*>(&b);
        reinterpret_cast<uint2*>(xs)[i] = pk;
    } else if (bx >= PREP_SPLIT0) {
        int i = (bx - PREP_SPLIT0) * 256 + tid;
        int p = i / WSZ, r = i - p * WSZ;
        const float* w = p == 0 ? w0 : p == 1 ? w1 : p == 2 ? w2 : w3;
        float v = w[r];
        __nv_bfloat16 h = __float2bfloat16(v);
        hi[i] = h;
        lo[i] = __float2bfloat16(v - __bfloat162float(h));
    } else if (bx >= 6) {
        int base = (bx - 6) * (Bq * HEADS * HD * HD / 2);
        for (int j = tid; j < Bq * HEADS * HD * HD / 2; j += 256)
            g_kvi[base + j] = 0;
    } else {
        int i = bx * 256 + tid;
        if (i < 4 * Cc) {
            int st = i / Cc, c = i - st * Cc;
            const float* ga = st == 0 ? g0 : st == 1 ? g1 : st == 2 ? g2 : g3;
            const float* be = st == 0 ? b0 : st == 1 ? b1 : st == 2 ? b2 : b3;
            const float* me = st == 0 ? m0 : st == 1 ? m1 : st == 2 ? m2 : m3;
            const float* va = st == 0 ? v0 : st == 1 ? v1 : st == 2 ? v2 : v3;
            float sv = ga[c] / sqrtf(va[c] + 1e-5f);
            s[i] = sv;
            t[i] = be[c] - me[c] * sv;
        }
    }
}

// ---------------- HMMA GEMM, 128x128, warp 64x32, k-chunk 64, 1 barrier/chunk
#define STG_B 49152            // per stage: A_hi 16K | A_lo 16K | B 16K
#define SMEM_GEMM (2*STG_B)    // 98304

__global__ __launch_bounds__(256, 2)
void gemm_hmma(const __nv_bfloat16* __restrict__ Whi, const __nv_bfloat16* __restrict__ Wlo,
               const __nv_bfloat16* __restrict__ X,
               __nv_bfloat16* __restrict__ oq, int8_t* __restrict__ ok8,
               int8_t* __restrict__ ov8, float* __restrict__ ofp,
               const float* __restrict__ sArr, const float* __restrict__ tArr,
               int mbase, int mode)
{
    extern __shared__ char smem[];
    const uint32_t sb = smem_u32(smem);
    const int tid = threadIdx.x, lane = tid & 31, wid = tid >> 5;
    const int wm = wid & 1, wn = wid >> 1;
    const int n0 = blockIdx.x * 128, m0 = mbase + blockIdx.y * 128, b = blockIdx.z;
    const __nv_bfloat16* Xb = X + (size_t)b * (Cc * Nn);

    float acc[4][4][4];
    #pragma unroll
    for (int t = 0; t < 4; ++t)
        #pragma unroll
        for (int u = 0; u < 4; ++u)
            #pragma unroll
            for (int e = 0; e < 4; ++e) acc[t][u][e] = 0.0f;

    auto load_chunk = [&](int kc, int st) {
        uint32_t base = sb + st * STG_B;
        #pragma unroll
        for (int p = 0; p < 4; ++p) {                   // A hi+lo: 128r x 8 chunks
            int idx = tid + p * 256;
            int row = idx >> 3, c = idx & 7;
            uint32_t so = row * 128 + ((c ^ (row & 7)) << 4);
            cp16(base + so, Whi + (size_t)(m0 + row) * Cc + kc * 64 + c * 8);
            cp16(base + 16384 + so, Wlo + (size_t)(m0 + row) * Cc + kc * 64 + c * 8);
        }
        #pragma unroll
        for (int p = 0; p < 4; ++p) {                   // B: 64 k-rows x 16 chunks
            int idx = tid + p * 256;
            int kr = idx >> 4, c = idx & 15;
            uint32_t so = kr * 256 + (((c & 8) | ((c & 7) ^ (kr & 7))) << 4);
            cp16(base + 32768 + so, Xb + (size_t)(kc * 64 + kr) * Nn + n0 + c * 8);
        }
        asm volatile("cp.async.commit_group;");
    };

    load_chunk(0, 0);
    const int sel = lane >> 3, l7 = lane & 7;

    for (int kc = 0; kc < 6; ++kc) {
        asm volatile("cp.async.wait_group 0;");
        __syncthreads();                       // RAW for chunk kc + WAR for kc+1's buffer
        if (kc + 1 < 6) load_chunk(kc + 1, (kc + 1) & 1);

        uint32_t base = sb + (kc & 1) * STG_B;

        #pragma unroll
        for (int h = 0; h < 4; ++h) {                   // 4 k16 halves per k64
            uint32_t bb[2][4];
            #pragma unroll
            for (int j = 0; j < 2; ++j) {
                int kr = h * 16 + (sel & 1) * 8 + l7;
                int nc = (wn * 32 + j * 16 + (sel >> 1) * 8) >> 3;
                uint32_t bd = base + 32768 + kr * 256 +
                              (((nc & 8) | ((nc & 7) ^ (kr & 7))) << 4);
                ldsm4t(bb[j], bd);
            }
            #pragma unroll
            for (int t = 0; t < 4; ++t) {
                int row = wm * 64 + t * 16 + (sel & 1) * 8 + l7;
                int kcx = h * 2 + (sel >> 1);
                uint32_t ad = base + row * 128 + ((kcx ^ (row & 7)) << 4);
                uint32_t ahi[4], alo[4];
                ldsm4(ahi, ad);
                #pragma unroll
                for (int u = 0; u < 4; ++u)
                    mma16816(acc[t][u], ahi, &bb[u >> 1][(u & 1) * 2]);
                ldsm4(alo, ad + 16384);
                #pragma unroll
                for (int u = 0; u < 4; ++u)
                    mma16816(acc[t][u], alo, &bb[u >> 1][(u & 1) * 2]);
            }
        }
    }
    // mode-0 staging (34.8 KB) fits in stage-0 buffer; final compute reads stage-1.

    if (mode == 0) {
        const int st = m0 / Cc;                      // 0=q, 1=k, 2=v
        const int mloc = m0 - st * Cc;
        __nv_bfloat16* sm = reinterpret_cast<__nv_bfloat16*>(smem);
        #pragma unroll
        for (int t = 0; t < 4; ++t) {
            int r0 = wm * 64 + t * 16 + (lane >> 2);
            float s0 = sArr[m0 + r0], t0 = tArr[m0 + r0];
            float s1 = sArr[m0 + r0 + 8], t1 = tArr[m0 + r0 + 8];
            #pragma unroll
            for (int u = 0; u < 4; ++u) {
                int col = wn * 32 + u * 8 + 2 * (lane & 3);
                __nv_bfloat162 p0 = __floats2bfloat162_rn(
                    spikef(acc[t][u][0] * s0 + t0), spikef(acc[t][u][1] * s0 + t0));
                __nv_bfloat162 p1 = __floats2bfloat162_rn(
                    spikef(acc[t][u][2] * s1 + t1), spikef(acc[t][u][3] * s1 + t1));
                *reinterpret_cast<__nv_bfloat162*>(sm + r0 * 136 + col) = p0;
                *reinterpret_cast<__nv_bfloat162*>(sm + (r0 + 8) * 136 + col) = p1;
            }
        }
        __syncthreads();
        if (st == 0) {
            __nv_bfloat16* Yb = oq + (size_t)b * (Cc * Nn);
            #pragma unroll
            for (int it = 0; it < 8; ++it) {
                int idx = tid + it * 256;
                int row = idx >> 4, ci = idx & 15;
                uint4 u4 = *reinterpret_cast<const uint4*>(sm + row * 136 + ci * 8);
                *reinterpret_cast<uint4*>(
                    Yb + (size_t)(mloc + row) * Nn + n0 + ci * 8) = u4;
            }
        } else {
            int8_t* Yb = (st == 1 ? ok8 : ov8) + (size_t)b * (Cc * Nn);
            #pragma unroll
            for (int it = 0; it < 8; ++it) {
                int idx = tid + it * 256;
                int row = idx >> 4, ci = idx & 15;
                uint4 u4 = *reinterpret_cast<const uint4*>(sm + row * 136 + ci * 8);
                const __nv_bfloat16* pb = reinterpret_cast<const __nv_bfloat16*>(&u4);
                uint32_t lo = 0, hi = 0;
                #pragma unroll
                for (int z = 0; z < 4; ++z)
                    lo |= ((uint32_t)(int)(__bfloat162float(pb[z]) * 4.0f)) << (8 * z);
                #pragma unroll
                for (int z = 0; z < 4; ++z)
                    hi |= ((uint32_t)(int)(__bfloat162float(pb[4 + z]) * 4.0f)) << (8 * z);
                uint2 pk = make_uint2(lo, hi);
                *reinterpret_cast<uint2*>(
                    Yb + (size_t)(mloc + row) * Nn + n0 + ci * 8) = pk;
            }
        }
    } else {
        float* Yb = ofp + (size_t)b * (Cc * Nn);
        const int mloc = m0 - 3 * Cc;
        #pragma unroll
        for (int t = 0; t < 4; ++t) {
            int r0 = wm * 64 + t * 16 + (lane >> 2);
            float s0 = sArr[m0 + r0], t0 = tArr[m0 + r0];
            float s1 = sArr[m0 + r0 + 8], t1 = tArr[m0 + r0 + 8];
            #pragma unroll
            for (int u = 0; u < 4; ++u) {
                int col = n0 + wn * 32 + u * 8 + 2 * (lane & 3);
                float2 p0 = make_float2(acc[t][u][0] * s0 + t0, acc[t][u][1] * s0 + t0);
                float2 p1 = make_float2(acc[t][u][2] * s1 + t1, acc[t][u][3] * s1 + t1);
                *reinterpret_cast<float2*>(Yb + (size_t)(mloc + r0) * Nn + col) = p0;
                *reinterpret_cast<float2*>(Yb + (size_t)(mloc + r0 + 8) * Nn + col) = p1;
            }
        }
    }
}

// ---------------- kv via dp4a: kv[b,h,d,e] = sum_n 4k*4v (exact s32) ---------
__global__ __launch_bounds__(256)
void kv_kernel() {
    const int chunk = blockIdx.x, h = blockIdx.y, b = blockIdx.z;
    const int* kp = reinterpret_cast<const int*>(
        g_ki8 + ((size_t)b * Cc + h * HD) * Nn) + chunk * 128;
    const int* vp = reinterpret_cast<const int*>(
        g_vi8 + ((size_t)b * Cc + h * HD) * Nn) + chunk * 128;

    __shared__ int ks[64][49];
    __shared__ int vs[64][49];

    const int tid = threadIdx.x;
    const int te = tid & 15, td = tid >> 4;
    int acc[3][3] = {};

    #pragma unroll
    for (int sub = 0; sub < 2; ++sub) {
        #pragma unroll
        for (int p = 0; p < 12; ++p) {
            int i = tid + p * 256;
            int d = i >> 6, w = i & 63;
            ks[w][d] = kp[(size_t)d * (Nn / 4) + sub * 64 + w];
            vs[w][d] = vp[(size_t)d * (Nn / 4) + sub * 64 + w];
        }
        __syncthreads();
        #pragma unroll 4
        for (int w = 0; w < 64; ++w) {
            int kd[3], ve[3];
            #pragma unroll
            for (int i = 0; i < 3; ++i) kd[i] = ks[w][td * 3 + i];
            #pragma unroll
            for (int i = 0; i < 3; ++i) ve[i] = vs[w][te * 3 + i];
            #pragma unroll
            for (int i = 0; i < 3; ++i)
                #pragma unroll
                for (int j = 0; j < 3; ++j)
                    acc[i][j] = dp4a_s(kd[i], ve[j], acc[i][j]);
        }
        __syncthreads();
    }
    int* kvp = g_kvi + (size_t)(b * HEADS + h) * HD * HD;
    #pragma unroll
    for (int i = 0; i < 3; ++i)
        #pragma unroll
        for (int j = 0; j < 3; ++j)
            atomicAdd(&kvp[(td * 3 + i) * HD + te * 3 + j], acc[i][j]);
}

// ---------------- kv_split: kvi -> 3 pre-swizzled bf16 digit planes ---------
// One element per thread; grid (9, 64). i = e*48 + d so the three 2B stores
// per thread are contiguous across the warp (coalesced 64B runs per e-row).
__global__ __launch_bounds__(256)
void kv_split() {
    const int bh = blockIdx.y;
    const int i = blockIdx.x * 256 + threadIdx.x;     // 0 .. 2303
    if (i >= HD * HD) return;
    const int e = i / HD, d = i - e * HD;
    const int* kvp = g_kvi + (size_t)bh * HD * HD;
    char* dst = g_kvp + (size_t)bh * 16128;

    float f = (float)kvp[d * HD + e];            // exact (< 2^24)
    __nv_bfloat16 hi = __float2bfloat16(f);
    float f1 = f - __bfloat162float(hi);         // exact
    __nv_bfloat16 mid = __float2bfloat16(f1);
    float f2 = f1 - __bfloat162float(mid);       // exact
    __nv_bfloat16 lo = __float2bfloat16(f2);
    char* base = dst + e * 112 + d * 2;
    *reinterpret_cast<__nv_bfloat16*>(base) = hi;
    *reinterpret_cast<__nv_bfloat16*>(base + 5376) = mid;
    *reinterpret_cast<__nv_bfloat16*>(base + 2 * 5376) = lo;
}

// ---------------- attn via HMMA: a = spike(mult16 * q @ kvi) -----------------
#define A_PITCH 112
#define A_PLANE (HD * A_PITCH)
#define Q_OFF   16384
#define ATTN_SMEM (Q_OFF + HD * 256)

__global__ __launch_bounds__(192)
void attn_hmma() {
    __shared__ char smem[ATTN_SMEM];
    const uint32_t sb = smem_u32(smem);
    const int tid = threadIdx.x, lane = tid & 31, wid = tid >> 5;
    const int wm = wid >> 1, wn = wid & 1;
    const int n0 = blockIdx.x * 128, h = blockIdx.y, b = blockIdx.z;

    // q tile [48 d][128 n] + pre-split kv planes, all via cp.async
    const __nv_bfloat16* qp = g_q + ((size_t)b * Cc + h * HD) * Nn + n0;
    #pragma unroll
    for (int p = 0; p < 4; ++p) {
        int idx = tid + p * 192;
        int d = idx >> 4, c = idx & 15;
        uint32_t so = Q_OFF + d * 256 + (((c & 8) | ((c & 7) ^ (d & 7))) << 4);
        cp16(sb + so, qp + (size_t)d * Nn + c * 8);
    }
    const char* kvsrc = g_kvp + (size_t)(b * HEADS + h) * 16128;
    #pragma unroll
    for (int p = 0; p < 6; ++p) {
        int idx = tid + p * 192;
        if (idx < 1008) cp16(sb + idx * 16, kvsrc + idx * 16);
    }
    asm volatile("cp.async.commit_group;");
    asm volatile("cp.async.wait_group 0;");
    __syncthreads();

    const int sel = lane >> 3, l7 = lane & 7;

    float acc[8][4];
    #pragma unroll
    for (int u = 0; u < 8; ++u)
        #pragma unroll
        for (int e = 0; e < 4; ++e) acc[u][e] = 0.0f;

    #pragma unroll
    for (int kk = 0; kk < 3; ++kk) {
        uint32_t bb[4][4];
        #pragma unroll
        for (int j = 0; j < 4; ++j) {
            int kr = kk * 16 + (sel & 1) * 8 + l7;
            int nc = (wn * 64 + j * 16 + (sel >> 1) * 8) >> 3;
            uint32_t bd = sb + Q_OFF + kr * 256 +
                          (((nc & 8) | ((nc & 7) ^ (kr & 7))) << 4);
            ldsm4t(bb[j], bd);
        }
        int row = wm * 16 + (sel & 1) * 8 + l7;
        uint32_t ad = sb + row * A_PITCH + (kk * 2 + (sel >> 1)) * 16;
        #pragma unroll
        for (int pl = 0; pl < 3; ++pl) {
            uint32_t A[4];
            ldsm4(A, ad + pl * A_PLANE);
            #pragma unroll
            for (int u = 0; u < 8; ++u)
                mma16816(acc[u], A, &bb[u >> 1][(u & 1) * 2]);
        }
    }

    __nv_bfloat16* ap = g_a + (size_t)b * (Cc * Nn);
    const float mult16 = 0.28867513459481287f * 0.0625f;
    const int r0 = h * HD + wm * 16 + (lane >> 2);
    #pragma unroll
    for (int u = 0; u < 8; ++u) {
        int col = n0 + wn * 64 + u * 8 + 2 * (lane & 3);
        __nv_bfloat162 p0 = __floats2bfloat162_rn(
            spikef(acc[u][0] * mult16), spikef(acc[u][1] * mult16));
        __nv_bfloat162 p1 = __floats2bfloat162_rn(
            spikef(acc[u][2] * mult16), spikef(acc[u][3] * mult16));
        *reinterpret_cast<__nv_bfloat162*>(ap + (size_t)r0 * Nn + col) = p0;
        *reinterpret_cast<__nv_bfloat162*>(ap + (size_t)(r0 + 8) * Nn + col) = p1;
    }
}

// ---------------- launch ----------------
extern "C" void kernel_launch(void* const* d_in, const int* in_sizes, int n_in,
                              void* d_out, int out_size) {
    const float* x = (const float*)d_in[0];
    __nv_bfloat16 *xs, *qb, *ab, *whi, *wlo;
    int8_t *k8, *v8;
    float *sarr, *tarr;
    cudaGetSymbolAddress((void**)&xs,  g_xs);
    cudaGetSymbolAddress((void**)&qb,  g_q);
    cudaGetSymbolAddress((void**)&k8,  g_ki8);
    cudaGetSymbolAddress((void**)&v8,  g_vi8);
    cudaGetSymbolAddress((void**)&ab,  g_a);
    cudaGetSymbolAddress((void**)&whi, g_whi);
    cudaGetSymbolAddress((void**)&wlo, g_wlo);
    cudaGetSymbolAddress((void**)&sarr, g_s);
    cudaGetSymbolAddress((void**)&tarr, g_t);

    cudaFuncSetAttribute(gemm_hmma, cudaFuncAttributeMaxDynamicSharedMemorySize, SMEM_GEMM);

    prep_all<<<PREP_BLOCKS, 256>>>(
        x, xs,
        (const float*)d_in[1], (const float*)d_in[6],
        (const float*)d_in[11], (const float*)d_in[16], whi, wlo,
        (const float*)d_in[2],  (const float*)d_in[3],  (const float*)d_in[4],  (const float*)d_in[5],
        (const float*)d_in[7],  (const float*)d_in[8],  (const float*)d_in[9],  (const float*)d_in[10],
        (const float*)d_in[12], (const float*)d_in[13], (const float*)d_in[14], (const float*)d_in[15],
        (const float*)d_in[17], (const float*)d_in[18], (const float*)d_in[19], (const float*)d_in[20],
        sarr, tarr);

    // fused QKV: stacked M = 1152
    gemm_hmma<<<dim3(Nn / 128, 9, Bq), 256, SMEM_GEMM>>>(
        whi, wlo, xs, qb, k8, v8, nullptr, sarr, tarr, 0, 0);

    kv_kernel<<<dim3(8, HEADS, Bq), 256>>>();
    kv_split<<<dim3(9, 64), 256>>>();
    attn_hmma<<<dim3(Nn / 128, HEADS, Bq), 192>>>();

    gemm_hmma<<<dim3(Nn / 128, 3, Bq), 256, SMEM_GEMM>>>(
        whi, wlo, ab, nullptr, nullptr, nullptr, (float*)d_out, sarr, tarr, 3 * Cc, 1);
}

// round 16
// speedup vs baseline: 1.0314x; 1.0022x over previous
#include <cuda_runtime.h>
#include <cuda_bf16.h>
#include <math.h>
#include <stdint.h>

#define Bq    8
#define Cc    384
#define Nn    4096
#define HEADS 8
#define HD    48
#define WSZ   (Cc*Cc)

// ---------------- scratch (device globals) ----------------
__device__ __nv_bfloat16 g_xs[(size_t)Bq*Cc*Nn];   // spike(x)  [b][c][n]
__device__ __nv_bfloat16 g_q [(size_t)Bq*Cc*Nn];   // spike-q bf16 (for attn)
__device__ int8_t        g_ki8[(size_t)Bq*Cc*Nn];  // 4*spike-k int (0..4)
__device__ int8_t        g_vi8[(size_t)Bq*Cc*Nn];
__device__ __nv_bfloat16 g_a [(size_t)Bq*Cc*Nn];
__device__ __nv_bfloat16 g_whi[4*WSZ];             // stacked rows: [1536][384]
__device__ __nv_bfloat16 g_wlo[4*WSZ];
__device__ int   g_kvi[Bq*HEADS*HD*HD];            // exact integer kv sums (16x)
__device__ char  g_kvp[64*16128];                  // pre-swizzled kv digit planes
__device__ float g_s [4*Cc];
__device__ float g_t [4*Cc];

__device__ __forceinline__ float spikef(float x) {
    return rintf(fminf(fmaxf(x, 0.0f), 4.0f)) * 0.25f;
}

// ---------------- PTX helpers (sm_80-class ISA, compiles on plain sm_103) ----
__device__ __forceinline__ uint32_t smem_u32(const void* p) {
    uint32_t a;
    asm("{ .reg .u64 t; cvta.to.shared.u64 t, %1; cvt.u32.u64 %0, t; }" : "=r"(a) : "l"(p));
    return a;
}
__device__ __forceinline__ void cp16(uint32_t s, const void* g) {
    asm volatile("cp.async.cg.shared.global [%0], [%1], 16;" :: "r"(s), "l"(g));
}
__device__ __forceinline__ void ldsm4(uint32_t* r, uint32_t a) {
    asm volatile("ldmatrix.sync.aligned.m8n8.x4.shared.b16 {%0,%1,%2,%3}, [%4];"
        : "=r"(r[0]), "=r"(r[1]), "=r"(r[2]), "=r"(r[3]) : "r"(a));
}
__device__ __forceinline__ void ldsm4t(uint32_t* r, uint32_t a) {
    asm volatile("ldmatrix.sync.aligned.m8n8.x4.trans.shared.b16 {%0,%1,%2,%3}, [%4];"
        : "=r"(r[0]), "=r"(r[1]), "=r"(r[2]), "=r"(r[3]) : "r"(a));
}
__device__ __forceinline__ void mma16816(float* d, const uint32_t* a, const uint32_t* b) {
    asm volatile(
        "mma.sync.aligned.m16n8k16.row.col.f32.bf16.bf16.f32 "
        "{%0,%1,%2,%3}, {%4,%5,%6,%7}, {%8,%9}, {%0,%1,%2,%3};"
        : "+f"(d[0]), "+f"(d[1]), "+f"(d[2]), "+f"(d[3])
        : "r"(a[0]), "r"(a[1]), "r"(a[2]), "r"(a[3]), "r"(b[0]), "r"(b[1]));
}
__device__ __forceinline__ int dp4a_s(int a, int b, int c) {
    asm("dp4a.s32.s32 %0, %1, %2, %3;" : "=r"(c) : "r"(a), "r"(b), "r"(c));
    return c;
}

// ---------------- prep_all: params + kv-zero + weight split + spike(x) ------
#define PREP_SPLIT0 8
#define PREP_SPIKE0 2312
#define PREP_BLOCKS 14600

__global__ __launch_bounds__(256)
void prep_all(
    const float* __restrict__ x, __nv_bfloat16* __restrict__ xs,
    const float* w0, const float* w1, const float* w2, const float* w3,
    __nv_bfloat16* __restrict__ hi, __nv_bfloat16* __restrict__ lo,
    const float* g0, const float* b0, const float* m0, const float* v0,
    const float* g1, const float* b1, const float* m1, const float* v1,
    const float* g2, const float* b2, const float* m2, const float* v2,
    const float* g3, const float* b3, const float* m3, const float* v3,
    float* __restrict__ s, float* __restrict__ t)
{
    const int bx = blockIdx.x, tid = threadIdx.x;
    if (bx >= PREP_SPIKE0) {
        int i = (bx - PREP_SPIKE0) * 256 + tid;
        float4 v = reinterpret_cast<const float4*>(x)[i];
        __nv_bfloat162 a = __floats2bfloat162_rn(spikef(v.x), spikef(v.y));
        __nv_bfloat162 b = __floats2bfloat162_rn(spikef(v.z), spikef(v.w));
        uint2 pk;
        pk.x = *reinterpret_cast<uint32_t*>(&a);
        pk.y = *reinterpret_cast<uint32_t*>(&b);
        reinterpret_cast<uint2*>(xs)[i] = pk;
    } else if (bx >= PREP_SPLIT0) {
        int i = (bx - PREP_SPLIT0) * 256 + tid;
        int p = i / WSZ, r = i - p * WSZ;
        const float* w = p == 0 ? w0 : p == 1 ? w1 : p == 2 ? w2 : w3;
        float v = w[r];
        __nv_bfloat16 h = __float2bfloat16(v);
        hi[i] = h;
        lo[i] = __float2bfloat16(v - __bfloat162float(h));
    } else if (bx >= 6) {
        int base = (bx - 6) * (Bq * HEADS * HD * HD / 2);
        for (int j = tid; j < Bq * HEADS * HD * HD / 2; j += 256)
            g_kvi[base + j] = 0;
    } else {
        int i = bx * 256 + tid;
        if (i < 4 * Cc) {
            int st = i / Cc, c = i - st * Cc;
            const float* ga = st == 0 ? g0 : st == 1 ? g1 : st == 2 ? g2 : g3;
            const float* be = st == 0 ? b0 : st == 1 ? b1 : st == 2 ? b2 : b3;
            const float* me = st == 0 ? m0 : st == 1 ? m1 : st == 2 ? m2 : m3;
            const float* va = st == 0 ? v0 : st == 1 ? v1 : st == 2 ? v2 : v3;
            float sv = ga[c] / sqrtf(va[c] + 1e-5f);
            s[i] = sv;
            t[i] = be[c] - me[c] * sv;
        }
    }
}

// ---------------- HMMA GEMM, 128x128, warp 64x32, k-chunk 64, 1 barrier/chunk
// B fragments preloaded in h-pairs to hide ldsm latency under mma issue.
#define STG_B 49152            // per stage: A_hi 16K | A_lo 16K | B 16K
#define SMEM_GEMM (2*STG_B)    // 98304

__global__ __launch_bounds__(256, 2)
void gemm_hmma(const __nv_bfloat16* __restrict__ Whi, const __nv_bfloat16* __restrict__ Wlo,
               const __nv_bfloat16* __restrict__ X,
               __nv_bfloat16* __restrict__ oq, int8_t* __restrict__ ok8,
               int8_t* __restrict__ ov8, float* __restrict__ ofp,
               const float* __restrict__ sArr, const float* __restrict__ tArr,
               int mbase, int mode)
{
    extern __shared__ char smem[];
    const uint32_t sb = smem_u32(smem);
    const int tid = threadIdx.x, lane = tid & 31, wid = tid >> 5;
    const int wm = wid & 1, wn = wid >> 1;
    const int n0 = blockIdx.x * 128, m0 = mbase + blockIdx.y * 128, b = blockIdx.z;
    const __nv_bfloat16* Xb = X + (size_t)b * (Cc * Nn);

    float acc[4][4][4];
    #pragma unroll
    for (int t = 0; t < 4; ++t)
        #pragma unroll
        for (int u = 0; u < 4; ++u)
            #pragma unroll
            for (int e = 0; e < 4; ++e) acc[t][u][e] = 0.0f;

    auto load_chunk = [&](int kc, int st) {
        uint32_t base = sb + st * STG_B;
        #pragma unroll
        for (int p = 0; p < 4; ++p) {                   // A hi+lo: 128r x 8 chunks
            int idx = tid + p * 256;
            int row = idx >> 3, c = idx & 7;
            uint32_t so = row * 128 + ((c ^ (row & 7)) << 4);
            cp16(base + so, Whi + (size_t)(m0 + row) * Cc + kc * 64 + c * 8);
            cp16(base + 16384 + so, Wlo + (size_t)(m0 + row) * Cc + kc * 64 + c * 8);
        }
        #pragma unroll
        for (int p = 0; p < 4; ++p) {                   // B: 64 k-rows x 16 chunks
            int idx = tid + p * 256;
            int kr = idx >> 4, c = idx & 15;
            uint32_t so = kr * 256 + (((c & 8) | ((c & 7) ^ (kr & 7))) << 4);
            cp16(base + 32768 + so, Xb + (size_t)(kc * 64 + kr) * Nn + n0 + c * 8);
        }
        asm volatile("cp.async.commit_group;");
    };

    load_chunk(0, 0);
    const int sel = lane >> 3, l7 = lane & 7;

    for (int kc = 0; kc < 6; ++kc) {
        asm volatile("cp.async.wait_group 0;");
        __syncthreads();
        if (kc + 1 < 6) load_chunk(kc + 1, (kc + 1) & 1);

        uint32_t base = sb + (kc & 1) * STG_B;

        #pragma unroll
        for (int hp = 0; hp < 2; ++hp) {                // h-pairs: (0,1), (2,3)
            uint32_t bb[2][2][4];                       // [h in pair][j][frag]
            #pragma unroll
            for (int hh = 0; hh < 2; ++hh)
                #pragma unroll
                for (int j = 0; j < 2; ++j) {
                    int kr = (hp * 2 + hh) * 16 + (sel & 1) * 8 + l7;
                    int nc = (wn * 32 + j * 16 + (sel >> 1) * 8) >> 3;
                    uint32_t bd = base + 32768 + kr * 256 +
                                  (((nc & 8) | ((nc & 7) ^ (kr & 7))) << 4);
                    ldsm4t(bb[hh][j], bd);
                }
            #pragma unroll
            for (int hh = 0; hh < 2; ++hh) {
                int h = hp * 2 + hh;
                #pragma unroll
                for (int t = 0; t < 4; ++t) {
                    int row = wm * 64 + t * 16 + (sel & 1) * 8 + l7;
                    int kcx = h * 2 + (sel >> 1);
                    uint32_t ad = base + row * 128 + ((kcx ^ (row & 7)) << 4);
                    uint32_t ahi[4], alo[4];
                    ldsm4(ahi, ad);
                    #pragma unroll
                    for (int u = 0; u < 4; ++u)
                        mma16816(acc[t][u], ahi, &bb[hh][u >> 1][(u & 1) * 2]);
                    ldsm4(alo, ad + 16384);
                    #pragma unroll
                    for (int u = 0; u < 4; ++u)
                        mma16816(acc[t][u], alo, &bb[hh][u >> 1][(u & 1) * 2]);
                }
            }
        }
    }
    // mode-0 staging (34.8 KB) fits in stage-0 buffer; final compute reads stage-1.

    if (mode == 0) {
        const int st = m0 / Cc;                      // 0=q, 1=k, 2=v
        const int mloc = m0 - st * Cc;
        __nv_bfloat16* sm = reinterpret_cast<__nv_bfloat16*>(smem);
        #pragma unroll
        for (int t = 0; t < 4; ++t) {
            int r0 = wm * 64 + t * 16 + (lane >> 2);
            float s0 = sArr[m0 + r0], t0 = tArr[m0 + r0];
            float s1 = sArr[m0 + r0 + 8], t1 = tArr[m0 + r0 + 8];
            #pragma unroll
            for (int u = 0; u < 4; ++u) {
                int col = wn * 32 + u * 8 + 2 * (lane & 3);
                __nv_bfloat162 p0 = __floats2bfloat162_rn(
                    spikef(acc[t][u][0] * s0 + t0), spikef(acc[t][u][1] * s0 + t0));
                __nv_bfloat162 p1 = __floats2bfloat162_rn(
                    spikef(acc[t][u][2] * s1 + t1), spikef(acc[t][u][3] * s1 + t1));
                *reinterpret_cast<__nv_bfloat162*>(sm + r0 * 136 + col) = p0;
                *reinterpret_cast<__nv_bfloat162*>(sm + (r0 + 8) * 136 + col) = p1;
            }
        }
        __syncthreads();
        if (st == 0) {
            __nv_bfloat16* Yb = oq + (size_t)b * (Cc * Nn);
            #pragma unroll
            for (int it = 0; it < 8; ++it) {
                int idx = tid + it * 256;
                int row = idx >> 4, ci = idx & 15;
                uint4 u4 = *reinterpret_cast<const uint4*>(sm + row * 136 + ci * 8);
                *reinterpret_cast<uint4*>(
                    Yb + (size_t)(mloc + row) * Nn + n0 + ci * 8) = u4;
            }
        } else {
            int8_t* Yb = (st == 1 ? ok8 : ov8) + (size_t)b * (Cc * Nn);
            #pragma unroll
            for (int it = 0; it < 8; ++it) {
                int idx = tid + it * 256;
                int row = idx >> 4, ci = idx & 15;
                uint4 u4 = *reinterpret_cast<const uint4*>(sm + row * 136 + ci * 8);
                const __nv_bfloat16* pb = reinterpret_cast<const __nv_bfloat16*>(&u4);
                uint32_t lo = 0, hi = 0;
                #pragma unroll
                for (int z = 0; z < 4; ++z)
                    lo |= ((uint32_t)(int)(__bfloat162float(pb[z]) * 4.0f)) << (8 * z);
                #pragma unroll
                for (int z = 0; z < 4; ++z)
                    hi |= ((uint32_t)(int)(__bfloat162float(pb[4 + z]) * 4.0f)) << (8 * z);
                uint2 pk = make_uint2(lo, hi);
                *reinterpret_cast<uint2*>(
                    Yb + (size_t)(mloc + row) * Nn + n0 + ci * 8) = pk;
            }
        }
    } else {
        float* Yb = ofp + (size_t)b * (Cc * Nn);
        const int mloc = m0 - 3 * Cc;
        #pragma unroll
        for (int t = 0; t < 4; ++t) {
            int r0 = wm * 64 + t * 16 + (lane >> 2);
            float s0 = sArr[m0 + r0], t0 = tArr[m0 + r0];
            float s1 = sArr[m0 + r0 + 8], t1 = tArr[m0 + r0 + 8];
            #pragma unroll
            for (int u = 0; u < 4; ++u) {
                int col = n0 + wn * 32 + u * 8 + 2 * (lane & 3);
                float2 p0 = make_float2(acc[t][u][0] * s0 + t0, acc[t][u][1] * s0 + t0);
                float2 p1 = make_float2(acc[t][u][2] * s1 + t1, acc[t][u][3] * s1 + t1);
                *reinterpret_cast<float2*>(Yb + (size_t)(mloc + r0) * Nn + col) = p0;
                *reinterpret_cast<float2*>(Yb + (size_t)(mloc + r0 + 8) * Nn + col) = p1;
            }
        }
    }
}

// ---------------- kv via dp4a: kv[b,h,d,e] = sum_n 4k*4v (exact s32) ---------
__global__ __launch_bounds__(256)
void kv_kernel() {
    const int chunk = blockIdx.x, h = blockIdx.y, b = blockIdx.z;
    const int* kp = reinterpret_cast<const int*>(
        g_ki8 + ((size_t)b * Cc + h * HD) * Nn) + chunk * 128;
    const int* vp = reinterpret_cast<const int*>(
        g_vi8 + ((size_t)b * Cc + h * HD) * Nn) + chunk * 128;

    __shared__ int ks[64][49];
    __shared__ int vs[64][49];

    const int tid = threadIdx.x;
    const int te = tid & 15, td = tid >> 4;
    int acc[3][3] = {};

    #pragma unroll
    for (int sub = 0; sub < 2; ++sub) {
        #pragma unroll
        for (int p = 0; p < 12; ++p) {
            int i = tid + p * 256;
            int d = i >> 6, w = i & 63;
            ks[w][d] = kp[(size_t)d * (Nn / 4) + sub * 64 + w];
            vs[w][d] = vp[(size_t)d * (Nn / 4) + sub * 64 + w];
        }
        __syncthreads();
        #pragma unroll 4
        for (int w = 0; w < 64; ++w) {
            int kd[3], ve[3];
            #pragma unroll
            for (int i = 0; i < 3; ++i) kd[i] = ks[w][td * 3 + i];
            #pragma unroll
            for (int i = 0; i < 3; ++i) ve[i] = vs[w][te * 3 + i];
            #pragma unroll
            for (int i = 0; i < 3; ++i)
                #pragma unroll
                for (int j = 0; j < 3; ++j)
                    acc[i][j] = dp4a_s(kd[i], ve[j], acc[i][j]);
        }
        __syncthreads();
    }
    int* kvp = g_kvi + (size_t)(b * HEADS + h) * HD * HD;
    #pragma unroll
    for (int i = 0; i < 3; ++i)
        #pragma unroll
        for (int j = 0; j < 3; ++j)
            atomicAdd(&kvp[(td * 3 + i) * HD + te * 3 + j], acc[i][j]);
}

// ---------------- kv_split: one element per thread ---------------------------
__global__ __launch_bounds__(256)
void kv_split() {
    const int bh = blockIdx.y;
    const int i = blockIdx.x * 256 + threadIdx.x;     // 0 .. 2303
    if (i >= HD * HD) return;
    const int e = i / HD, d = i - e * HD;
    const int* kvp = g_kvi + (size_t)bh * HD * HD;
    char* dst = g_kvp + (size_t)bh * 16128;

    float f = (float)kvp[d * HD + e];            // exact (< 2^24)
    __nv_bfloat16 hi = __float2bfloat16(f);
    float f1 = f - __bfloat162float(hi);         // exact
    __nv_bfloat16 mid = __float2bfloat16(f1);
    float f2 = f1 - __bfloat162float(mid);       // exact
    __nv_bfloat16 lo = __float2bfloat16(f2);
    char* base = dst + e * 112 + d * 2;
    *reinterpret_cast<__nv_bfloat16*>(base) = hi;
    *reinterpret_cast<__nv_bfloat16*>(base + 5376) = mid;
    *reinterpret_cast<__nv_bfloat16*>(base + 2 * 5376) = lo;
}

// ---------------- attn via HMMA, n-tile 256 ----------------------------------
#define A_PITCH 112
#define A_PLANE (HD * A_PITCH)
#define Q_OFF   16384
#define ATTN_SMEM (Q_OFF + HD * 512)      // 16384 + 24576 = 40960

__global__ __launch_bounds__(192)
void attn_hmma() {
    __shared__ char smem[ATTN_SMEM];
    const uint32_t sb = smem_u32(smem);
    const int tid = threadIdx.x, lane = tid & 31, wid = tid >> 5;
    const int wm = wid >> 1, wn = wid & 1;       // 3 e-rows x 2 n-halves (128 each)
    const int n0 = blockIdx.x * 256, h = blockIdx.y, b = blockIdx.z;

    // q tile [48 d][256 n] (512B rows, 32-chunk swizzle) + kv planes
    const __nv_bfloat16* qp = g_q + ((size_t)b * Cc + h * HD) * Nn + n0;
    #pragma unroll
    for (int p = 0; p < 8; ++p) {
        int idx = tid + p * 192;                 // 1536 chunks
        int d = idx >> 5, c = idx & 31;
        uint32_t so = Q_OFF + d * 512 + (((c & 24) | ((c & 7) ^ (d & 7))) << 4);
        cp16(sb + so, qp + (size_t)d * Nn + c * 8);
    }
    const char* kvsrc = g_kvp + (size_t)(b * HEADS + h) * 16128;
    #pragma unroll
    for (int p = 0; p < 6; ++p) {
        int idx = tid + p * 192;
        if (idx < 1008) cp16(sb + idx * 16, kvsrc + idx * 16);
    }
    asm volatile("cp.async.commit_group;");
    asm volatile("cp.async.wait_group 0;");
    __syncthreads();

    const int sel = lane >> 3, l7 = lane & 7;

    float acc[16][4];
    #pragma unroll
    for (int u = 0; u < 16; ++u)
        #pragma unroll
        for (int e = 0; e < 4; ++e) acc[u][e] = 0.0f;

    #pragma unroll
    for (int kk = 0; kk < 3; ++kk) {
        uint32_t bb[8][4];
        #pragma unroll
        for (int j = 0; j < 8; ++j) {            // n128 = 8 x n16
            int kr = kk * 16 + (sel & 1) * 8 + l7;
            int nc = (wn * 128 + j * 16 + (sel >> 1) * 8) >> 3;
            uint32_t bd = sb + Q_OFF + kr * 512 +
                          (((nc & 24) | ((nc & 7) ^ (kr & 7))) << 4);
            ldsm4t(bb[j], bd);
        }
        int row = wm * 16 + (sel & 1) * 8 + l7;
        uint32_t ad = sb + row * A_PITCH + (kk * 2 + (sel >> 1)) * 16;
        #pragma unroll
        for (int pl = 0; pl < 3; ++pl) {
            uint32_t A[4];
            ldsm4(A, ad + pl * A_PLANE);
            #pragma unroll
            for (int u = 0; u < 16; ++u)
                mma16816(acc[u], A, &bb[u >> 1][(u & 1) * 2]);
        }
    }

    __nv_bfloat16* ap = g_a + (size_t)b * (Cc * Nn);
    const float mult16 = 0.28867513459481287f * 0.0625f;
    const int r0 = h * HD + wm * 16 + (lane >> 2);
    #pragma unroll
    for (int u = 0; u < 16; ++u) {
        int col = n0 + wn * 128 + u * 8 + 2 * (lane & 3);
        __nv_bfloat162 p0 = __floats2bfloat162_rn(
            spikef(acc[u][0] * mult16), spikef(acc[u][1] * mult16));
        __nv_bfloat162 p1 = __floats2bfloat162_rn(
            spikef(acc[u][2] * mult16), spikef(acc[u][3] * mult16));
        *reinterpret_cast<__nv_bfloat162*>(ap + (size_t)r0 * Nn + col) = p0;
        *reinterpret_cast<__nv_bfloat162*>(ap + (size_t)(r0 + 8) * Nn + col) = p1;
    }
}

// ---------------- launch ----------------
extern "C" void kernel_launch(void* const* d_in, const int* in_sizes, int n_in,
                              void* d_out, int out_size) {
    const float* x = (const float*)d_in[0];
    __nv_bfloat16 *xs, *qb, *ab, *whi, *wlo;
    int8_t *k8, *v8;
    float *sarr, *tarr;
    cudaGetSymbolAddress((void**)&xs,  g_xs);
    cudaGetSymbolAddress((void**)&qb,  g_q);
    cudaGetSymbolAddress((void**)&k8,  g_ki8);
    cudaGetSymbolAddress((void**)&v8,  g_vi8);
    cudaGetSymbolAddress((void**)&ab,  g_a);
    cudaGetSymbolAddress((void**)&whi, g_whi);
    cudaGetSymbolAddress((void**)&wlo, g_wlo);
    cudaGetSymbolAddress((void**)&sarr, g_s);
    cudaGetSymbolAddress((void**)&tarr, g_t);

    cudaFuncSetAttribute(gemm_hmma, cudaFuncAttributeMaxDynamicSharedMemorySize, SMEM_GEMM);

    prep_all<<<PREP_BLOCKS, 256>>>(
        x, xs,
        (const float*)d_in[1], (const float*)d_in[6],
        (const float*)d_in[11], (const float*)d_in[16], whi, wlo,
        (const float*)d_in[2],  (const float*)d_in[3],  (const float*)d_in[4],  (const float*)d_in[5],
        (const float*)d_in[7],  (const float*)d_in[8],  (const float*)d_in[9],  (const float*)d_in[10],
        (const float*)d_in[12], (const float*)d_in[13], (const float*)d_in[14], (const float*)d_in[15],
        (const float*)d_in[17], (const float*)d_in[18], (const float*)d_in[19], (const float*)d_in[20],
        sarr, tarr);

    // fused QKV: stacked M = 1152
    gemm_hmma<<<dim3(Nn / 128, 9, Bq), 256, SMEM_GEMM>>>(
        whi, wlo, xs, qb, k8, v8, nullptr, sarr, tarr, 0, 0);

    kv_kernel<<<dim3(8, HEADS, Bq), 256>>>();
    kv_split<<<dim3(9, 64), 256>>>();
    attn_hmma<<<dim3(Nn / 256, HEADS, Bq), 192>>>();

    gemm_hmma<<<dim3(Nn / 128, 3, Bq), 256, SMEM_GEMM>>>(
        whi, wlo, ab, nullptr, nullptr, nullptr, (float*)d_out, sarr, tarr, 3 * Cc, 1);
}